// round 1
// baseline (speedup 1.0000x reference)
#include <cuda_runtime.h>
#include <math.h>

#define BATCH 2
#define SEQ   2048
#define NTOK  (BATCH*SEQ)      // 4096
#define DIM   1024
#define HEADS 16
#define HDIM  64
#define WIN   128
#define SCALE 0.125f           // 1/sqrt(64)

// Scratch (device globals; no allocation allowed)
__device__ float g_qin[NTOK*DIM];
__device__ float g_q  [NTOK*DIM];
__device__ float g_k  [NTOK*DIM];
__device__ float g_v  [NTOK*DIM];
__device__ float g_ao [NTOK*DIM];

// ---------------------------------------------------------------------------
// RoPE: q_in[t, h*64+i]      = x1*cos - x2*sin
//       q_in[t, h*64+i+32]   = x2*cos + x1*sin      (i in 0..31)
// cos/sin of (s * theta^{-i/32})
// ---------------------------------------------------------------------------
__global__ void rope_kernel(const float* __restrict__ x) {
    int idx = blockIdx.x * blockDim.x + threadIdx.x;   // NTOK*512
    if (idx >= NTOK * 512) return;
    int t   = idx >> 9;
    int rem = idx & 511;
    int h   = rem >> 5;
    int i   = rem & 31;
    int s   = t & (SEQ - 1);

    // inv_freq = 10000^{-(2i/64)} = exp(-(i/32)*ln(10000))
    float inv = expf(-(float)i * (9.210340371976184f / 32.0f));
    float ang = (float)s * inv;
    float sn, cs;
    sincosf(ang, &sn, &cs);

    const float* xp = x     + (size_t)t * DIM + h * HDIM;
    float*       qp = g_qin + (size_t)t * DIM + h * HDIM;
    float x1 = xp[i];
    float x2 = xp[i + 32];
    qp[i]      = x1 * cs - x2 * sn;
    qp[i + 32] = x2 * cs + x1 * sn;
}

// ---------------------------------------------------------------------------
// SGEMM: C[4096,1024] = A[4096,1024] * W[1024,1024]   (all row-major, fp32)
// 128x128 block tile, BK=8, 8x8 per thread, 256 threads, reg prefetch.
// ---------------------------------------------------------------------------
__global__ __launch_bounds__(256)
void sgemm128(const float* __restrict__ A, const float* __restrict__ Bw,
              float* __restrict__ C) {
    __shared__ float As[8][128];
    __shared__ float Bs[8][128];

    const int tid  = threadIdx.x;
    const int row0 = blockIdx.y * 128;
    const int col0 = blockIdx.x * 128;
    const int tx   = tid & 15;     // 0..15 -> 8 cols each
    const int ty   = tid >> 4;     // 0..15 -> 8 rows each

    // A tile load mapping: 128 rows x 8 cols, one float4 per thread
    const int am = tid >> 1;             // 0..127
    const int ak = (tid & 1) * 4;        // 0 or 4
    // B tile load mapping: 8 rows x 128 cols, one float4 per thread
    const int bk = tid >> 5;             // 0..7
    const int bn = (tid & 31) * 4;       // 0..124

    const float* Aptr = A  + (size_t)(row0 + am) * DIM + ak;
    const float* Bptr = Bw + (size_t)bk * DIM + col0 + bn;

    float acc[8][8];
#pragma unroll
    for (int i = 0; i < 8; i++)
#pragma unroll
        for (int j = 0; j < 8; j++) acc[i][j] = 0.0f;

    float4 av = *(const float4*)(Aptr);
    float4 bv = *(const float4*)(Bptr);

    for (int k0 = 0; k0 < DIM; k0 += 8) {
        __syncthreads();
        As[ak + 0][am] = av.x;
        As[ak + 1][am] = av.y;
        As[ak + 2][am] = av.z;
        As[ak + 3][am] = av.w;
        *(float4*)&Bs[bk][bn] = bv;
        __syncthreads();

        if (k0 + 8 < DIM) {
            av = *(const float4*)(Aptr + (k0 + 8));
            bv = *(const float4*)(Bptr + (size_t)(k0 + 8) * DIM);
        }

#pragma unroll
        for (int kk = 0; kk < 8; kk++) {
            float a[8], b[8];
#pragma unroll
            for (int i = 0; i < 4; i++) {
                float4 t0 = *(const float4*)&As[kk][ty * 8 + 4 * (i >> 1)]; (void)t0;
            }
            // simple scalar reads (broadcast / conflict-free patterns)
#pragma unroll
            for (int i = 0; i < 8; i++) a[i] = As[kk][ty * 8 + i];
#pragma unroll
            for (int j = 0; j < 8; j++) b[j] = Bs[kk][tx * 8 + j];
#pragma unroll
            for (int i = 0; i < 8; i++)
#pragma unroll
                for (int j = 0; j < 8; j++)
                    acc[i][j] = fmaf(a[i], b[j], acc[i][j]);
        }
    }

#pragma unroll
    for (int i = 0; i < 8; i++) {
        float* cp = C + (size_t)(row0 + ty * 8 + i) * DIM + col0 + tx * 8;
        *(float4*)(cp)     = make_float4(acc[i][0], acc[i][1], acc[i][2], acc[i][3]);
        *(float4*)(cp + 4) = make_float4(acc[i][4], acc[i][5], acc[i][6], acc[i][7]);
    }
}

// ---------------------------------------------------------------------------
// Sliding-window attention. One CTA per (q-tile of 128, head, batch).
// Key tiles: qt-1 (valid iff r > tid), qt (all valid), qt+1 (valid iff r < tid).
// No-max softmax: scores are bounded (|q||k|/8 << 88), exp cannot overflow,
// and masked entries (-1e9 in the reference) underflow to exactly 0.
// ---------------------------------------------------------------------------
extern __shared__ float sh_attn[];   // Ks[128*64] then Vs[128*64]

__global__ __launch_bounds__(128)
void attn_kernel() {
    float* Ks = sh_attn;
    float* Vs = sh_attn + 128 * 64;

    const int qt  = blockIdx.x;
    const int h   = blockIdx.y;
    const int b   = blockIdx.z;
    const int tid = threadIdx.x;
    const int qi  = qt * 128 + tid;            // query position in sequence

    const float* qp = g_q + (size_t)(b * SEQ + qi) * DIM + h * HDIM;
    float qreg[64];
#pragma unroll
    for (int d = 0; d < 64; d += 4) {
        float4 v4 = *(const float4*)(qp + d);
        qreg[d] = v4.x; qreg[d+1] = v4.y; qreg[d+2] = v4.z; qreg[d+3] = v4.w;
    }

    float acc[64];
#pragma unroll
    for (int d = 0; d < 64; d++) acc[d] = 0.0f;
    float l = 0.0f;

    const int ntiles = SEQ / 128;
    for (int pass = 0; pass < 3; pass++) {
        const int kt = qt - 1 + pass;
        if (kt < 0 || kt >= ntiles) continue;

        __syncthreads();
        const float* kb = g_k + (size_t)(b * SEQ + kt * 128) * DIM + h * HDIM;
        const float* vb = g_v + (size_t)(b * SEQ + kt * 128) * DIM + h * HDIM;
#pragma unroll
        for (int i = 0; i < 16; i++) {
            int idx = i * 128 + tid;          // 0..2047
            int r   = idx >> 4;
            int d4  = (idx & 15) << 2;
            *(float4*)&Ks[r * 64 + d4] = *(const float4*)(kb + (size_t)r * DIM + d4);
            *(float4*)&Vs[r * 64 + d4] = *(const float4*)(vb + (size_t)r * DIM + d4);
        }
        __syncthreads();

        const int rlo = (pass == 0) ? 1 : 0;
        const int rhi = (pass == 2) ? 127 : 128;
        for (int r = rlo; r < rhi; r++) {
            bool valid = (pass == 1) || (pass == 0 ? (r > tid) : (r < tid));
            if (valid) {
                const float* kr = &Ks[r * 64];
                float dot = 0.0f;
#pragma unroll
                for (int d = 0; d < 64; d++) dot = fmaf(qreg[d], kr[d], dot);
                float p = __expf(dot * SCALE);
                l += p;
                const float* vr = &Vs[r * 64];
#pragma unroll
                for (int d = 0; d < 64; d++) acc[d] = fmaf(p, vr[d], acc[d]);
            }
        }
    }

    const float inv = 1.0f / l;
    float* op = g_ao + (size_t)(b * SEQ + qi) * DIM + h * HDIM;
#pragma unroll
    for (int d = 0; d < 64; d += 4) {
        *(float4*)(op + d) = make_float4(acc[d] * inv, acc[d+1] * inv,
                                         acc[d+2] * inv, acc[d+3] * inv);
    }
}

// ---------------------------------------------------------------------------
extern "C" void kernel_launch(void* const* d_in, const int* in_sizes, int n_in,
                              void* d_out, int out_size) {
    const float* x  = (const float*)d_in[0];  // hidden_states [2,2048,1024]
    const float* Wq = (const float*)d_in[1];  // [1024,16,64] = [1024,1024]
    const float* Wk = (const float*)d_in[2];
    const float* Wv = (const float*)d_in[3];
    const float* Wo = (const float*)d_in[4];  // [16,64,1024] = [1024,1024]
    float* out = (float*)d_out;

    float *qin, *q, *k, *v, *ao;
    cudaGetSymbolAddress((void**)&qin, g_qin);
    cudaGetSymbolAddress((void**)&q,   g_q);
    cudaGetSymbolAddress((void**)&k,   g_k);
    cudaGetSymbolAddress((void**)&v,   g_v);
    cudaGetSymbolAddress((void**)&ao,  g_ao);

    cudaFuncSetAttribute(attn_kernel,
                         cudaFuncAttributeMaxDynamicSharedMemorySize, 65536);

    // 1. RoPE
    rope_kernel<<<(NTOK * 512 + 255) / 256, 256>>>(x);

    // 2. Projections
    dim3 ggrid(DIM / 128, NTOK / 128);
    sgemm128<<<ggrid, 256>>>(qin, Wq, q);
    sgemm128<<<ggrid, 256>>>(qin, Wk, k);
    sgemm128<<<ggrid, 256>>>(x,   Wv, v);

    // 3. Windowed attention
    attn_kernel<<<dim3(SEQ / 128, HEADS, BATCH), 128, 65536>>>();

    // 4. Output projection -> d_out
    sgemm128<<<ggrid, 256>>>(ao, Wo, out);
    (void)in_sizes; (void)n_in; (void)out_size;
}

// round 4
// speedup vs baseline: 1.9797x; 1.9797x over previous
#include <cuda_runtime.h>
#include <math.h>
#include <cstdint>

#define BATCH 2
#define SEQ   2048
#define NTOK  (BATCH*SEQ)      // 4096
#define DIM   1024
#define HEADS 16
#define HDIM  64
#define WIN   128
#define SCALE 0.125f           // 1/sqrt(64)

// Scratch (device globals; no allocation allowed)
__device__ float g_qin[NTOK*DIM];
__device__ float g_q  [NTOK*DIM];
__device__ float g_k  [NTOK*DIM];
__device__ float g_v  [NTOK*DIM];
__device__ float g_ao [NTOK*DIM];

__device__ __forceinline__ uint32_t to_tf32(float x) {
    uint32_t u;
    asm("cvt.rna.tf32.f32 %0, %1;" : "=r"(u) : "f"(x));
    return u;
}

// ===========================================================================
// RoPE
// ===========================================================================
__global__ void rope_kernel(const float* __restrict__ x) {
    int idx = blockIdx.x * blockDim.x + threadIdx.x;   // NTOK*512
    if (idx >= NTOK * 512) return;
    int t   = idx >> 9;
    int rem = idx & 511;
    int h   = rem >> 5;
    int i   = rem & 31;
    int s   = t & (SEQ - 1);

    float inv = expf(-(float)i * (9.210340371976184f / 32.0f));
    float ang = (float)s * inv;
    float sn, cs;
    sincosf(ang, &sn, &cs);

    const float* xp = x     + (size_t)t * DIM + h * HDIM;
    float*       qp = g_qin + (size_t)t * DIM + h * HDIM;
    float x1 = xp[i];
    float x2 = xp[i + 32];
    qp[i]      = x1 * cs - x2 * sn;
    qp[i + 32] = x2 * cs + x1 * sn;
}

// ===========================================================================
// TF32 mma.sync GEMM: C[4096,1024] = A[4096,1024] * W[1024,1024]
// CTA 128x128, BK=32, 256 threads (2x4 warps, each 64x32).
// m16n8k8 tf32 HMMA, double-buffered DYNAMIC smem, reg prefetch.
// A smem: [128][36]  (stride 36: 4*gid+tig -> conflict-free frag reads)
// B smem: [32][136]  (stride 136: 8*tig+gid -> conflict-free frag reads)
// W is [K,N] row-major == col-major N-major operand, no transpose needed.
// ===========================================================================
#define ASTR 36
#define BSTR 136
#define A_ELEMS (128 * ASTR)            // per buffer
#define B_ELEMS (32 * BSTR)             // per buffer
#define GEMM_SMEM_BYTES ((2 * A_ELEMS + 2 * B_ELEMS) * 4)   // 71680

extern __shared__ uint32_t gemm_sm[];

__device__ __forceinline__ void mma_tf32(float* c, const uint32_t* a, const uint32_t* b) {
    asm volatile(
        "mma.sync.aligned.m16n8k8.row.col.f32.tf32.tf32.f32 "
        "{%0,%1,%2,%3}, {%4,%5,%6,%7}, {%8,%9}, {%0,%1,%2,%3};"
        : "+f"(c[0]), "+f"(c[1]), "+f"(c[2]), "+f"(c[3])
        : "r"(a[0]), "r"(a[1]), "r"(a[2]), "r"(a[3]), "r"(b[0]), "r"(b[1]));
}

__global__ __launch_bounds__(256)
void gemm_tf32(const float* __restrict__ A, const float* __restrict__ W,
               float* __restrict__ C) {
    uint32_t* As = gemm_sm;                    // [2][A_ELEMS]
    uint32_t* Bs = gemm_sm + 2 * A_ELEMS;      // [2][B_ELEMS]

    const int tid  = threadIdx.x;
    const int wid  = tid >> 5;
    const int lane = tid & 31;
    const int gid  = lane >> 2;    // 0..7
    const int tig  = lane & 3;     // 0..3
    const int wm   = wid >> 2;     // 0..1
    const int wn   = wid & 3;      // 0..3
    const int col0 = blockIdx.x * 128;
    const int row0 = blockIdx.y * 128;

    // Global load mappings (per chunk of BK=32):
    // A: 1024 float4 slots; 4/thread. idx -> m = idx>>3 (0..127), k4 = idx&7
    // B: 1024 float4 slots; 4/thread. idx -> k = idx>>5 (0..31),  n4 = idx&31
    float4 av[4], bv[4];

    const float* Abase = A + (size_t)row0 * DIM;
    const float* Wbase = W + col0;

#define LOAD_CHUNK(k0)                                                           \
    {                                                                            \
        _Pragma("unroll")                                                        \
        for (int i = 0; i < 4; i++) {                                            \
            int idx = i * 256 + tid;                                             \
            int m = idx >> 3, k4 = idx & 7;                                      \
            av[i] = *(const float4*)(Abase + (size_t)m * DIM + (k0) + k4 * 4);   \
            int kk = idx >> 5, n4 = idx & 31;                                    \
            bv[i] = *(const float4*)(Wbase + (size_t)((k0) + kk) * DIM + n4 * 4);\
        }                                                                        \
    }

#define STORE_CHUNK(p)                                                           \
    {                                                                            \
        _Pragma("unroll")                                                        \
        for (int i = 0; i < 4; i++) {                                            \
            int idx = i * 256 + tid;                                             \
            int m = idx >> 3, k4 = idx & 7;                                      \
            uint4* ap = (uint4*)&As[(p) * A_ELEMS + m * ASTR + k4 * 4];          \
            *ap = make_uint4(to_tf32(av[i].x), to_tf32(av[i].y),                 \
                             to_tf32(av[i].z), to_tf32(av[i].w));                \
            int kk = idx >> 5, n4 = idx & 31;                                    \
            uint4* bp = (uint4*)&Bs[(p) * B_ELEMS + kk * BSTR + n4 * 4];         \
            *bp = make_uint4(to_tf32(bv[i].x), to_tf32(bv[i].y),                 \
                             to_tf32(bv[i].z), to_tf32(bv[i].w));                \
        }                                                                        \
    }

    float acc[4][4][4];
#pragma unroll
    for (int i = 0; i < 4; i++)
#pragma unroll
        for (int j = 0; j < 4; j++)
#pragma unroll
            for (int r = 0; r < 4; r++) acc[i][j][r] = 0.0f;

    LOAD_CHUNK(0);
    STORE_CHUNK(0);
    __syncthreads();

    const int NCHUNK = DIM / 32;   // 32
    for (int c = 0; c < NCHUNK; c++) {
        const int p = c & 1;
        if (c + 1 < NCHUNK) LOAD_CHUNK((c + 1) * 32);

        const uint32_t* Ab = &As[p * A_ELEMS];
        const uint32_t* Bb = &Bs[p * B_ELEMS];
#pragma unroll
        for (int s = 0; s < 4; s++) {          // k substeps of 8
            const int ks = s * 8;
            uint32_t af[4][4], bf[4][2];
#pragma unroll
            for (int i = 0; i < 4; i++) {
                int rb = wm * 64 + i * 16;
                af[i][0] = Ab[(rb + gid)     * ASTR + ks + tig];
                af[i][1] = Ab[(rb + gid + 8) * ASTR + ks + tig];
                af[i][2] = Ab[(rb + gid)     * ASTR + ks + tig + 4];
                af[i][3] = Ab[(rb + gid + 8) * ASTR + ks + tig + 4];
            }
#pragma unroll
            for (int j = 0; j < 4; j++) {
                int cb = wn * 32 + j * 8;
                bf[j][0] = Bb[(ks + tig)     * BSTR + cb + gid];
                bf[j][1] = Bb[(ks + tig + 4) * BSTR + cb + gid];
            }
#pragma unroll
            for (int i = 0; i < 4; i++)
#pragma unroll
                for (int j = 0; j < 4; j++)
                    mma_tf32(acc[i][j], af[i], bf[j]);
        }

        if (c + 1 < NCHUNK) {
            __syncthreads();
            STORE_CHUNK(p ^ 1);
            __syncthreads();
        }
    }

    // Epilogue: c0:(gid, 2*tig) c1:(gid, 2*tig+1) c2/c3: row +8
#pragma unroll
    for (int i = 0; i < 4; i++) {
        int r0 = row0 + wm * 64 + i * 16 + gid;
#pragma unroll
        for (int j = 0; j < 4; j++) {
            int cc = col0 + wn * 32 + j * 8 + tig * 2;
            *(float2*)(C + (size_t)r0 * DIM + cc)       = make_float2(acc[i][j][0], acc[i][j][1]);
            *(float2*)(C + (size_t)(r0 + 8) * DIM + cc) = make_float2(acc[i][j][2], acc[i][j][3]);
        }
    }
}

// ===========================================================================
// Sliding-window attention (unchanged)
// ===========================================================================
extern __shared__ float sh_attn[];   // Ks[128*64] then Vs[128*64]

__global__ __launch_bounds__(128)
void attn_kernel() {
    float* Ks = sh_attn;
    float* Vs = sh_attn + 128 * 64;

    const int qt  = blockIdx.x;
    const int h   = blockIdx.y;
    const int b   = blockIdx.z;
    const int tid = threadIdx.x;
    const int qi  = qt * 128 + tid;

    const float* qp = g_q + (size_t)(b * SEQ + qi) * DIM + h * HDIM;
    float qreg[64];
#pragma unroll
    for (int d = 0; d < 64; d += 4) {
        float4 v4 = *(const float4*)(qp + d);
        qreg[d] = v4.x; qreg[d+1] = v4.y; qreg[d+2] = v4.z; qreg[d+3] = v4.w;
    }

    float acc[64];
#pragma unroll
    for (int d = 0; d < 64; d++) acc[d] = 0.0f;
    float l = 0.0f;

    const int ntiles = SEQ / 128;
    for (int pass = 0; pass < 3; pass++) {
        const int kt = qt - 1 + pass;
        if (kt < 0 || kt >= ntiles) continue;

        __syncthreads();
        const float* kb = g_k + (size_t)(b * SEQ + kt * 128) * DIM + h * HDIM;
        const float* vb = g_v + (size_t)(b * SEQ + kt * 128) * DIM + h * HDIM;
#pragma unroll
        for (int i = 0; i < 16; i++) {
            int idx = i * 128 + tid;
            int r   = idx >> 4;
            int d4  = (idx & 15) << 2;
            *(float4*)&Ks[r * 64 + d4] = *(const float4*)(kb + (size_t)r * DIM + d4);
            *(float4*)&Vs[r * 64 + d4] = *(const float4*)(vb + (size_t)r * DIM + d4);
        }
        __syncthreads();

        const int rlo = (pass == 0) ? 1 : 0;
        const int rhi = (pass == 2) ? 127 : 128;
        for (int r = rlo; r < rhi; r++) {
            bool valid = (pass == 1) || (pass == 0 ? (r > tid) : (r < tid));
            if (valid) {
                const float* kr = &Ks[r * 64];
                float dot = 0.0f;
#pragma unroll
                for (int d = 0; d < 64; d++) dot = fmaf(qreg[d], kr[d], dot);
                float p = __expf(dot * SCALE);
                l += p;
                const float* vr = &Vs[r * 64];
#pragma unroll
                for (int d = 0; d < 64; d++) acc[d] = fmaf(p, vr[d], acc[d]);
            }
        }
    }

    const float inv = 1.0f / l;
    float* op = g_ao + (size_t)(b * SEQ + qi) * DIM + h * HDIM;
#pragma unroll
    for (int d = 0; d < 64; d += 4) {
        *(float4*)(op + d) = make_float4(acc[d] * inv, acc[d+1] * inv,
                                         acc[d+2] * inv, acc[d+3] * inv);
    }
}

// ===========================================================================
extern "C" void kernel_launch(void* const* d_in, const int* in_sizes, int n_in,
                              void* d_out, int out_size) {
    const float* x  = (const float*)d_in[0];
    const float* Wq = (const float*)d_in[1];
    const float* Wk = (const float*)d_in[2];
    const float* Wv = (const float*)d_in[3];
    const float* Wo = (const float*)d_in[4];
    float* out = (float*)d_out;

    float *qin, *q, *k, *v, *ao;
    cudaGetSymbolAddress((void**)&qin, g_qin);
    cudaGetSymbolAddress((void**)&q,   g_q);
    cudaGetSymbolAddress((void**)&k,   g_k);
    cudaGetSymbolAddress((void**)&v,   g_v);
    cudaGetSymbolAddress((void**)&ao,  g_ao);

    cudaFuncSetAttribute(attn_kernel,
                         cudaFuncAttributeMaxDynamicSharedMemorySize, 65536);
    cudaFuncSetAttribute(gemm_tf32,
                         cudaFuncAttributeMaxDynamicSharedMemorySize, GEMM_SMEM_BYTES);

    // 1. RoPE
    rope_kernel<<<(NTOK * 512 + 255) / 256, 256>>>(x);

    // 2. Projections (tf32 HMMA)
    dim3 ggrid(DIM / 128, NTOK / 128);
    gemm_tf32<<<ggrid, 256, GEMM_SMEM_BYTES>>>(qin, Wq, q);
    gemm_tf32<<<ggrid, 256, GEMM_SMEM_BYTES>>>(qin, Wk, k);
    gemm_tf32<<<ggrid, 256, GEMM_SMEM_BYTES>>>(x,   Wv, v);

    // 3. Windowed attention
    attn_kernel<<<dim3(SEQ / 128, HEADS, BATCH), 128, 65536>>>();

    // 4. Output projection -> d_out
    gemm_tf32<<<ggrid, 256, GEMM_SMEM_BYTES>>>(ao, Wo, out);
    (void)in_sizes; (void)n_in; (void)out_size;
}

// round 5
// speedup vs baseline: 2.3072x; 1.1654x over previous
#include <cuda_runtime.h>
#include <math.h>
#include <cstdint>

#define BATCH 2
#define SEQ   2048
#define NTOK  (BATCH*SEQ)      // 4096
#define DIM   1024
#define HEADS 16
#define HDIM  64
#define WIN   128
#define SCALE 0.125f           // 1/sqrt(64)

typedef unsigned long long u64;

// Scratch (device globals; no allocation allowed)
__device__ float g_qin[NTOK*DIM];
__device__ float g_q  [NTOK*DIM];
__device__ float g_k  [NTOK*DIM];
__device__ float g_v  [NTOK*DIM];
__device__ float g_ao [NTOK*DIM];

__device__ __forceinline__ uint32_t to_tf32(float x) {
    uint32_t u;
    asm("cvt.rna.tf32.f32 %0, %1;" : "=r"(u) : "f"(x));
    return u;
}
__device__ __forceinline__ u64 ffma2(u64 a, u64 b, u64 c) {
    u64 d;
    asm("fma.rn.f32x2 %0, %1, %2, %3;" : "=l"(d) : "l"(a), "l"(b), "l"(c));
    return d;
}

// ===========================================================================
// RoPE
// ===========================================================================
__global__ void rope_kernel(const float* __restrict__ x) {
    int idx = blockIdx.x * blockDim.x + threadIdx.x;   // NTOK*512
    if (idx >= NTOK * 512) return;
    int t   = idx >> 9;
    int rem = idx & 511;
    int h   = rem >> 5;
    int i   = rem & 31;
    int s   = t & (SEQ - 1);

    float inv = expf(-(float)i * (9.210340371976184f / 32.0f));
    float ang = (float)s * inv;
    float sn, cs;
    sincosf(ang, &sn, &cs);

    const float* xp = x     + (size_t)t * DIM + h * HDIM;
    float*       qp = g_qin + (size_t)t * DIM + h * HDIM;
    float x1 = xp[i];
    float x2 = xp[i + 32];
    qp[i]      = x1 * cs - x2 * sn;
    qp[i + 32] = x2 * cs + x1 * sn;
}

// ===========================================================================
// TF32 mma.sync GEMM: C[4096,1024] = A[4096,1024] * W[1024,1024]
// CTA tile 256x128 (grid = 8x16 = 128 CTAs = ONE wave on 148 SMs).
// 256 threads = 8 warps in 4x2; warp tile 64x64 (4x8 m16n8k8 tiles).
// BK=32, double-buffered dynamic smem, reg prefetch, tf32 rna rounding.
// A smem: [256][36]  (stride 36: bank 4*gid+tig, conflict-free)
// B smem: [32][136]  (stride 136: bank 8*tig+gid, conflict-free)
// ===========================================================================
#define ASTR 36
#define BSTR 136
#define A_ELEMS (256 * ASTR)            // 9216 u32 per buffer
#define B_ELEMS (32 * BSTR)             // 4352 u32 per buffer
#define GEMM_SMEM_BYTES ((2 * A_ELEMS + 2 * B_ELEMS) * 4)   // 108544

extern __shared__ uint32_t gemm_sm[];

__device__ __forceinline__ void mma_tf32(float* c, const uint32_t* a, const uint32_t* b) {
    asm volatile(
        "mma.sync.aligned.m16n8k8.row.col.f32.tf32.tf32.f32 "
        "{%0,%1,%2,%3}, {%4,%5,%6,%7}, {%8,%9}, {%0,%1,%2,%3};"
        : "+f"(c[0]), "+f"(c[1]), "+f"(c[2]), "+f"(c[3])
        : "r"(a[0]), "r"(a[1]), "r"(a[2]), "r"(a[3]), "r"(b[0]), "r"(b[1]));
}

__global__ __launch_bounds__(256)
void gemm_tf32(const float* __restrict__ A, const float* __restrict__ W,
               float* __restrict__ C) {
    uint32_t* As = gemm_sm;                    // [2][A_ELEMS]
    uint32_t* Bs = gemm_sm + 2 * A_ELEMS;      // [2][B_ELEMS]

    const int tid  = threadIdx.x;
    const int wid  = tid >> 5;
    const int lane = tid & 31;
    const int gid  = lane >> 2;    // 0..7
    const int tig  = lane & 3;     // 0..3
    const int wm   = wid >> 1;     // 0..3  (x64 rows)
    const int wn   = wid & 1;      // 0..1  (x64 cols)
    const int col0 = blockIdx.x * 128;
    const int row0 = blockIdx.y * 256;

    // Global load mappings per BK=32 chunk:
    // A: 256x32 = 2048 float4 slots; 8/thread. idx -> m = idx>>3, k4 = idx&7
    // B: 32x128 = 1024 float4 slots; 4/thread. idx -> k = idx>>5, n4 = idx&31
    float4 av[8], bv[4];

    const float* Abase = A + (size_t)row0 * DIM;
    const float* Wbase = W + col0;

#define LOAD_CHUNK(k0)                                                           \
    {                                                                            \
        _Pragma("unroll")                                                        \
        for (int i = 0; i < 8; i++) {                                            \
            int idx = i * 256 + tid;                                             \
            int m = idx >> 3, k4 = idx & 7;                                      \
            av[i] = *(const float4*)(Abase + (size_t)m * DIM + (k0) + k4 * 4);   \
        }                                                                        \
        _Pragma("unroll")                                                        \
        for (int i = 0; i < 4; i++) {                                            \
            int idx = i * 256 + tid;                                             \
            int kk = idx >> 5, n4 = idx & 31;                                    \
            bv[i] = *(const float4*)(Wbase + (size_t)((k0) + kk) * DIM + n4 * 4);\
        }                                                                        \
    }

#define STORE_CHUNK(p)                                                           \
    {                                                                            \
        _Pragma("unroll")                                                        \
        for (int i = 0; i < 8; i++) {                                            \
            int idx = i * 256 + tid;                                             \
            int m = idx >> 3, k4 = idx & 7;                                      \
            uint4* ap = (uint4*)&As[(p) * A_ELEMS + m * ASTR + k4 * 4];          \
            *ap = make_uint4(to_tf32(av[i].x), to_tf32(av[i].y),                 \
                             to_tf32(av[i].z), to_tf32(av[i].w));                \
        }                                                                        \
        _Pragma("unroll")                                                        \
        for (int i = 0; i < 4; i++) {                                            \
            int idx = i * 256 + tid;                                             \
            int kk = idx >> 5, n4 = idx & 31;                                    \
            uint4* bp = (uint4*)&Bs[(p) * B_ELEMS + kk * BSTR + n4 * 4];         \
            *bp = make_uint4(to_tf32(bv[i].x), to_tf32(bv[i].y),                 \
                             to_tf32(bv[i].z), to_tf32(bv[i].w));                \
        }                                                                        \
    }

    float acc[4][8][4];
#pragma unroll
    for (int i = 0; i < 4; i++)
#pragma unroll
        for (int j = 0; j < 8; j++)
#pragma unroll
            for (int r = 0; r < 4; r++) acc[i][j][r] = 0.0f;

    LOAD_CHUNK(0);
    STORE_CHUNK(0);
    __syncthreads();

    const int NCHUNK = DIM / 32;   // 32
    for (int c = 0; c < NCHUNK; c++) {
        const int p = c & 1;
        if (c + 1 < NCHUNK) LOAD_CHUNK((c + 1) * 32);

        const uint32_t* Ab = &As[p * A_ELEMS];
        const uint32_t* Bb = &Bs[p * B_ELEMS];
#pragma unroll
        for (int s = 0; s < 4; s++) {          // k substeps of 8
            const int ks = s * 8;
            uint32_t af[4][4], bf[8][2];
#pragma unroll
            for (int i = 0; i < 4; i++) {
                int rb = wm * 64 + i * 16;
                af[i][0] = Ab[(rb + gid)     * ASTR + ks + tig];
                af[i][1] = Ab[(rb + gid + 8) * ASTR + ks + tig];
                af[i][2] = Ab[(rb + gid)     * ASTR + ks + tig + 4];
                af[i][3] = Ab[(rb + gid + 8) * ASTR + ks + tig + 4];
            }
#pragma unroll
            for (int j = 0; j < 8; j++) {
                int cb = wn * 64 + j * 8;
                bf[j][0] = Bb[(ks + tig)     * BSTR + cb + gid];
                bf[j][1] = Bb[(ks + tig + 4) * BSTR + cb + gid];
            }
#pragma unroll
            for (int i = 0; i < 4; i++)
#pragma unroll
                for (int j = 0; j < 8; j++)
                    mma_tf32(acc[i][j], af[i], bf[j]);
        }

        if (c + 1 < NCHUNK) {
            __syncthreads();
            STORE_CHUNK(p ^ 1);
            __syncthreads();
        }
    }

    // Epilogue: c0:(gid, 2*tig) c1:(gid, 2*tig+1) c2/c3: row +8
#pragma unroll
    for (int i = 0; i < 4; i++) {
        int r0 = row0 + wm * 64 + i * 16 + gid;
#pragma unroll
        for (int j = 0; j < 8; j++) {
            int cc = col0 + wn * 64 + j * 8 + tig * 2;
            *(float2*)(C + (size_t)r0 * DIM + cc)       = make_float2(acc[i][j][0], acc[i][j][1]);
            *(float2*)(C + (size_t)(r0 + 8) * DIM + cc) = make_float2(acc[i][j][2], acc[i][j][3]);
        }
    }
}

// ===========================================================================
// Sliding-window attention, packed f32x2 FFMA body.
// One CTA per (q-tile of 128, head, batch); thread = one query row.
// ===========================================================================
extern __shared__ float sh_attn[];   // Ks[128*64] then Vs[128*64]

__global__ __launch_bounds__(128)
void attn_kernel() {
    float* Ks = sh_attn;
    float* Vs = sh_attn + 128 * 64;

    const int qt  = blockIdx.x;
    const int h   = blockIdx.y;
    const int b   = blockIdx.z;
    const int tid = threadIdx.x;
    const int qi  = qt * 128 + tid;

    const float* qp = g_q + (size_t)(b * SEQ + qi) * DIM + h * HDIM;
    u64 q2[32];
#pragma unroll
    for (int d = 0; d < 16; d++) {
        float4 v4 = *(const float4*)(qp + d * 4);
        q2[d * 2]     = *(const u64*)&v4.x;
        q2[d * 2 + 1] = *(const u64*)&v4.z;
    }

    u64 acc2[32];
#pragma unroll
    for (int d = 0; d < 32; d++) acc2[d] = 0ULL;
    float l = 0.0f;

    const int ntiles = SEQ / 128;
    for (int pass = 0; pass < 3; pass++) {
        const int kt = qt - 1 + pass;
        if (kt < 0 || kt >= ntiles) continue;

        __syncthreads();
        const float* kb = g_k + (size_t)(b * SEQ + kt * 128) * DIM + h * HDIM;
        const float* vb = g_v + (size_t)(b * SEQ + kt * 128) * DIM + h * HDIM;
#pragma unroll
        for (int i = 0; i < 16; i++) {
            int idx = i * 128 + tid;
            int r   = idx >> 4;
            int d4  = (idx & 15) << 2;
            *(float4*)&Ks[r * 64 + d4] = *(const float4*)(kb + (size_t)r * DIM + d4);
            *(float4*)&Vs[r * 64 + d4] = *(const float4*)(vb + (size_t)r * DIM + d4);
        }
        __syncthreads();

        const int rlo = (pass == 0) ? 1 : 0;
        const int rhi = (pass == 2) ? 127 : 128;
        for (int r = rlo; r < rhi; r++) {
            bool valid = (pass == 1) || (pass == 0 ? (r > tid) : (r < tid));
            if (valid) {
                const u64* kr = (const u64*)&Ks[r * 64];
                u64 d2 = 0ULL;
#pragma unroll
                for (int d = 0; d < 32; d++) d2 = ffma2(q2[d], kr[d], d2);
                float2 dp = *(float2*)&d2;
                float p = __expf((dp.x + dp.y) * SCALE);
                l += p;
                float2 pp = make_float2(p, p);
                u64 p2 = *(u64*)&pp;
                const u64* vr = (const u64*)&Vs[r * 64];
#pragma unroll
                for (int d = 0; d < 32; d++) acc2[d] = ffma2(p2, vr[d], acc2[d]);
            }
        }
    }

    const float inv = 1.0f / l;
    float* op = g_ao + (size_t)(b * SEQ + qi) * DIM + h * HDIM;
#pragma unroll
    for (int d = 0; d < 32; d++) {
        float2 a = *(float2*)&acc2[d];
        *(float2*)(op + d * 2) = make_float2(a.x * inv, a.y * inv);
    }
}

// ===========================================================================
extern "C" void kernel_launch(void* const* d_in, const int* in_sizes, int n_in,
                              void* d_out, int out_size) {
    const float* x  = (const float*)d_in[0];
    const float* Wq = (const float*)d_in[1];
    const float* Wk = (const float*)d_in[2];
    const float* Wv = (const float*)d_in[3];
    const float* Wo = (const float*)d_in[4];
    float* out = (float*)d_out;

    float *qin, *q, *k, *v, *ao;
    cudaGetSymbolAddress((void**)&qin, g_qin);
    cudaGetSymbolAddress((void**)&q,   g_q);
    cudaGetSymbolAddress((void**)&k,   g_k);
    cudaGetSymbolAddress((void**)&v,   g_v);
    cudaGetSymbolAddress((void**)&ao,  g_ao);

    cudaFuncSetAttribute(attn_kernel,
                         cudaFuncAttributeMaxDynamicSharedMemorySize, 65536);
    cudaFuncSetAttribute(gemm_tf32,
                         cudaFuncAttributeMaxDynamicSharedMemorySize, GEMM_SMEM_BYTES);

    // 1. RoPE
    rope_kernel<<<(NTOK * 512 + 255) / 256, 256>>>(x);

    // 2. Projections (tf32 HMMA, one-wave grid)
    dim3 ggrid(DIM / 128, NTOK / 256);
    gemm_tf32<<<ggrid, 256, GEMM_SMEM_BYTES>>>(qin, Wq, q);
    gemm_tf32<<<ggrid, 256, GEMM_SMEM_BYTES>>>(qin, Wk, k);
    gemm_tf32<<<ggrid, 256, GEMM_SMEM_BYTES>>>(x,   Wv, v);

    // 3. Windowed attention (f32x2)
    attn_kernel<<<dim3(SEQ / 128, HEADS, BATCH), 128, 65536>>>();

    // 4. Output projection -> d_out
    gemm_tf32<<<ggrid, 256, GEMM_SMEM_BYTES>>>(ao, Wo, out);
    (void)in_sizes; (void)n_in; (void)out_size;
}

// round 6
// speedup vs baseline: 2.3851x; 1.0338x over previous
#include <cuda_runtime.h>
#include <math.h>
#include <cstdint>

#define BATCH 2
#define SEQ   2048
#define NTOK  (BATCH*SEQ)      // 4096
#define DIM   1024
#define HEADS 16
#define HDIM  64
#define WIN   128
#define SCALE 0.125f           // 1/sqrt(64)

typedef unsigned long long u64;

// Scratch (device globals; no allocation allowed)
__device__ float g_qin[NTOK*DIM];    // rope output, tf32-rounded
__device__ float g_xr [NTOK*DIM];    // x, tf32-rounded
__device__ float g_q  [NTOK*DIM];
__device__ float g_k  [NTOK*DIM];
__device__ float g_v  [NTOK*DIM];
__device__ float g_ao [NTOK*DIM];    // attention out, tf32-rounded
__device__ float g_wr [4*DIM*DIM];   // W^T, tf32-rounded: [mat][n][k]

__device__ __forceinline__ uint32_t to_tf32(float x) {
    uint32_t u;
    asm("cvt.rna.tf32.f32 %0, %1;" : "=r"(u) : "f"(x));
    return u;
}
__device__ __forceinline__ u64 ffma2(u64 a, u64 b, u64 c) {
    u64 d;
    asm("fma.rn.f32x2 %0, %1, %2, %3;" : "=l"(d) : "l"(a), "l"(b), "l"(c));
    return d;
}

#define CPA(dst, src) \
    asm volatile("cp.async.cg.shared.global [%0], [%1], 16;" :: "r"(dst), "l"(src) : "memory")
#define CPC() asm volatile("cp.async.commit_group;" ::: "memory")
#define CPW(n) asm volatile("cp.async.wait_group %0;" :: "n"(n) : "memory")
#define LDM4(r0, r1, r2, r3, a) \
    asm volatile("ldmatrix.sync.aligned.m8n8.x4.shared.b16 {%0,%1,%2,%3}, [%4];" \
        : "=r"(r0), "=r"(r1), "=r"(r2), "=r"(r3) : "r"(a))

__device__ __forceinline__ uint32_t smem_u32(const void* p) {
    uint32_t a;
    asm("{ .reg .u64 t; cvta.to.shared.u64 t, %1; cvt.u32.u64 %0, t; }" : "=r"(a) : "l"(p));
    return a;
}

// ===========================================================================
// Prep: transpose + tf32-round all 4 weight matrices ([k][n] -> [n][k])
// ===========================================================================
__global__ void prep_w(const float* __restrict__ w0, const float* __restrict__ w1,
                       const float* __restrict__ w2, const float* __restrict__ w3) {
    __shared__ float t[32][33];
    const int z = blockIdx.z;
    const float* w = (z == 0) ? w0 : (z == 1) ? w1 : (z == 2) ? w2 : w3;
    const int k0 = blockIdx.y * 32, n0 = blockIdx.x * 32;
    for (int r = threadIdx.y; r < 32; r += 8)
        t[r][threadIdx.x] = w[(size_t)(k0 + r) * DIM + n0 + threadIdx.x];
    __syncthreads();
    float* o = g_wr + (size_t)z * DIM * DIM;
    for (int r = threadIdx.y; r < 32; r += 8)
        o[(size_t)(n0 + r) * DIM + k0 + threadIdx.x] =
            __uint_as_float(to_tf32(t[threadIdx.x][r]));
}

__global__ void prep_x(const float* __restrict__ x) {
    int i = blockIdx.x * blockDim.x + threadIdx.x;     // 1M float4
    float4 v = *(const float4*)(x + (size_t)i * 4);
    v.x = __uint_as_float(to_tf32(v.x)); v.y = __uint_as_float(to_tf32(v.y));
    v.z = __uint_as_float(to_tf32(v.z)); v.w = __uint_as_float(to_tf32(v.w));
    *(float4*)(g_xr + (size_t)i * 4) = v;
}

// ===========================================================================
// RoPE (writes tf32-rounded qin)
// ===========================================================================
__global__ void rope_kernel(const float* __restrict__ x) {
    int idx = blockIdx.x * blockDim.x + threadIdx.x;   // NTOK*512
    if (idx >= NTOK * 512) return;
    int t   = idx >> 9;
    int rem = idx & 511;
    int h   = rem >> 5;
    int i   = rem & 31;
    int s   = t & (SEQ - 1);

    float inv = expf(-(float)i * (9.210340371976184f / 32.0f));
    float ang = (float)s * inv;
    float sn, cs;
    sincosf(ang, &sn, &cs);

    const float* xp = x     + (size_t)t * DIM + h * HDIM;
    float*       qp = g_qin + (size_t)t * DIM + h * HDIM;
    float x1 = xp[i];
    float x2 = xp[i + 32];
    qp[i]      = __uint_as_float(to_tf32(x1 * cs - x2 * sn));
    qp[i + 32] = __uint_as_float(to_tf32(x2 * cs + x1 * sn));
}

// ===========================================================================
// TF32 GEMM v3: C[4096,1024] = A * W   (A rounded [m][k], Wt rounded [n][k])
// CTA 256x128, BK=32, 256 threads, 8 warps 4x2, warp tile 64x64.
// 3-stage cp.async pipeline; ldmatrix.x4 fragment loads; both smem tiles
// [rows][36] (row stride 144B -> conflict-free cp.async + ldmatrix).
// ===========================================================================
#define RSTR 36
#define A_BYTES (256 * RSTR * 4)       // 36864
#define B_BYTES (128 * RSTR * 4)       // 18432
#define SSZ     (A_BYTES + B_BYTES)    // 55296
#define GEMM_SMEM_BYTES (3 * SSZ)      // 165888
#define NCHUNK  (DIM / 32)             // 32

extern __shared__ uint32_t dsm[];

__device__ __forceinline__ void mma_tf32(float* c, const uint32_t* a, const uint32_t* b) {
    asm volatile(
        "mma.sync.aligned.m16n8k8.row.col.f32.tf32.tf32.f32 "
        "{%0,%1,%2,%3}, {%4,%5,%6,%7}, {%8,%9}, {%0,%1,%2,%3};"
        : "+f"(c[0]), "+f"(c[1]), "+f"(c[2]), "+f"(c[3])
        : "r"(a[0]), "r"(a[1]), "r"(a[2]), "r"(a[3]), "r"(b[0]), "r"(b[1]));
}

__device__ __forceinline__ void gemm_body(const float* __restrict__ A,
                                          const float* __restrict__ Wt,
                                          float* __restrict__ C,
                                          int row0, int col0) {
    const int tid  = threadIdx.x;
    const int wid  = tid >> 5;
    const int lane = tid & 31;
    const int gid  = lane >> 2;
    const int tig  = lane & 3;
    const int wm   = wid >> 1;     // 0..3
    const int wn   = wid & 1;      // 0..1
    const int mi   = lane >> 3;    // ldmatrix matrix index
    const int lr   = lane & 7;

    const uint32_t sb = smem_u32(dsm);

    // cp.async mappings
    const int am = tid >> 3;           // wait: A has 2048 float4/stage, 8/thread
    // per-iter: idx = it*256+tid -> m = idx>>3, k4 = idx&7

    // ldmatrix per-lane offsets (bytes, within a stage)
    const uint32_t a_lane = ((wm * 64 + (mi & 1) * 8 + lr) * RSTR + (mi >> 1) * 4) * 4;
    const uint32_t b_lane = ((wn * 64 + (mi >> 1) * 8 + lr) * RSTR + (mi & 1) * 4) * 4;

    float acc[4][8][4];
#pragma unroll
    for (int i = 0; i < 4; i++)
#pragma unroll
        for (int j = 0; j < 8; j++)
#pragma unroll
            for (int r = 0; r < 4; r++) acc[i][j][r] = 0.0f;

#define ISSUE_STAGE(s, c)                                                        \
    {                                                                            \
        uint32_t ab = sb + (s) * SSZ;                                            \
        _Pragma("unroll")                                                        \
        for (int it = 0; it < 8; it++) {                                         \
            int idx = it * 256 + tid;                                            \
            int m = idx >> 3, k4 = idx & 7;                                      \
            CPA(ab + m * 144 + k4 * 16,                                          \
                A + (size_t)(row0 + m) * DIM + (c) * 32 + k4 * 4);               \
        }                                                                        \
        uint32_t bb = ab + A_BYTES;                                              \
        _Pragma("unroll")                                                        \
        for (int it = 0; it < 4; it++) {                                         \
            int idx = it * 256 + tid;                                            \
            int n = idx >> 3, k4 = idx & 7;                                      \
            CPA(bb + n * 144 + k4 * 16,                                          \
                Wt + (size_t)(col0 + n) * DIM + (c) * 32 + k4 * 4);              \
        }                                                                        \
        CPC();                                                                   \
    }

    ISSUE_STAGE(0, 0);
    ISSUE_STAGE(1, 1);

    int s = 0;
    for (int c = 0; c < NCHUNK; c++) {
        CPW(1);
        __syncthreads();
        if (c + 2 < NCHUNK) {
            int sn = (s + 2 >= 3) ? s - 1 : s + 2;
            ISSUE_STAGE(sn, c + 2);
        }

        const uint32_t abase = sb + s * SSZ;
        const uint32_t bbase = abase + A_BYTES;
#pragma unroll
        for (int ss = 0; ss < 4; ss++) {
            const int ksf = ss * 8 * 4;          // byte offset of k substep
            uint32_t af[4][4], bf[8][2];
#pragma unroll
            for (int i = 0; i < 4; i++)
                LDM4(af[i][0], af[i][1], af[i][2], af[i][3],
                     abase + a_lane + i * (16 * RSTR * 4) + ksf);
#pragma unroll
            for (int jj = 0; jj < 4; jj++)
                LDM4(bf[2 * jj][0], bf[2 * jj][1], bf[2 * jj + 1][0], bf[2 * jj + 1][1],
                     bbase + b_lane + jj * (16 * RSTR * 4) + ksf);
#pragma unroll
            for (int i = 0; i < 4; i++)
#pragma unroll
                for (int j = 0; j < 8; j++)
                    mma_tf32(acc[i][j], af[i], bf[j]);
        }
        s = (s + 1 == 3) ? 0 : s + 1;
    }

    // Epilogue
#pragma unroll
    for (int i = 0; i < 4; i++) {
        int r0 = row0 + wm * 64 + i * 16 + gid;
#pragma unroll
        for (int j = 0; j < 8; j++) {
            int cc = col0 + wn * 64 + j * 8 + tig * 2;
            *(float2*)(C + (size_t)r0 * DIM + cc)       = make_float2(acc[i][j][0], acc[i][j][1]);
            *(float2*)(C + (size_t)(r0 + 8) * DIM + cc) = make_float2(acc[i][j][2], acc[i][j][3]);
        }
    }
    (void)am; (void)tig; (void)gid;
}

__global__ __launch_bounds__(256)
void gemm_qkv() {
    const int mi   = blockIdx.x >> 3;            // 0=Q 1=K 2=V
    const int col0 = (blockIdx.x & 7) * 128;
    const int row0 = blockIdx.y * 256;
    const float* A  = (mi < 2) ? g_qin : g_xr;
    float*       C  = (mi == 0) ? g_q : (mi == 1) ? g_k : g_v;
    const float* Wt = g_wr + (size_t)mi * DIM * DIM;
    gemm_body(A, Wt, C, row0, col0);
}

__global__ __launch_bounds__(256)
void gemm_out(float* __restrict__ out) {
    const int col0 = blockIdx.x * 128;
    const int row0 = blockIdx.y * 256;
    gemm_body(g_ao, g_wr + (size_t)3 * DIM * DIM, out, row0, col0);
}

// ===========================================================================
// Sliding-window attention, packed f32x2 FFMA body (unchanged except
// tf32-rounded output for the final GEMM).
// ===========================================================================
extern __shared__ float sh_attn[];   // Ks[128*64] then Vs[128*64]

__global__ __launch_bounds__(128)
void attn_kernel() {
    float* Ks = sh_attn;
    float* Vs = sh_attn + 128 * 64;

    const int qt  = blockIdx.x;
    const int h   = blockIdx.y;
    const int b   = blockIdx.z;
    const int tid = threadIdx.x;
    const int qi  = qt * 128 + tid;

    const float* qp = g_q + (size_t)(b * SEQ + qi) * DIM + h * HDIM;
    u64 q2[32];
#pragma unroll
    for (int d = 0; d < 16; d++) {
        float4 v4 = *(const float4*)(qp + d * 4);
        q2[d * 2]     = *(const u64*)&v4.x;
        q2[d * 2 + 1] = *(const u64*)&v4.z;
    }

    u64 acc2[32];
#pragma unroll
    for (int d = 0; d < 32; d++) acc2[d] = 0ULL;
    float l = 0.0f;

    const int ntiles = SEQ / 128;
    for (int pass = 0; pass < 3; pass++) {
        const int kt = qt - 1 + pass;
        if (kt < 0 || kt >= ntiles) continue;

        __syncthreads();
        const float* kb = g_k + (size_t)(b * SEQ + kt * 128) * DIM + h * HDIM;
        const float* vb = g_v + (size_t)(b * SEQ + kt * 128) * DIM + h * HDIM;
#pragma unroll
        for (int i = 0; i < 16; i++) {
            int idx = i * 128 + tid;
            int r   = idx >> 4;
            int d4  = (idx & 15) << 2;
            *(float4*)&Ks[r * 64 + d4] = *(const float4*)(kb + (size_t)r * DIM + d4);
            *(float4*)&Vs[r * 64 + d4] = *(const float4*)(vb + (size_t)r * DIM + d4);
        }
        __syncthreads();

        const int rlo = (pass == 0) ? 1 : 0;
        const int rhi = (pass == 2) ? 127 : 128;
        for (int r = rlo; r < rhi; r++) {
            bool valid = (pass == 1) || (pass == 0 ? (r > tid) : (r < tid));
            if (valid) {
                const u64* kr = (const u64*)&Ks[r * 64];
                u64 d2 = 0ULL;
#pragma unroll
                for (int d = 0; d < 32; d++) d2 = ffma2(q2[d], kr[d], d2);
                float2 dp = *(float2*)&d2;
                float p = __expf((dp.x + dp.y) * SCALE);
                l += p;
                float2 pp = make_float2(p, p);
                u64 p2 = *(u64*)&pp;
                const u64* vr = (const u64*)&Vs[r * 64];
#pragma unroll
                for (int d = 0; d < 32; d++) acc2[d] = ffma2(p2, vr[d], acc2[d]);
            }
        }
    }

    const float inv = 1.0f / l;
    float* op = g_ao + (size_t)(b * SEQ + qi) * DIM + h * HDIM;
#pragma unroll
    for (int d = 0; d < 32; d++) {
        float2 a = *(float2*)&acc2[d];
        *(float2*)(op + d * 2) = make_float2(__uint_as_float(to_tf32(a.x * inv)),
                                             __uint_as_float(to_tf32(a.y * inv)));
    }
}

// ===========================================================================
extern "C" void kernel_launch(void* const* d_in, const int* in_sizes, int n_in,
                              void* d_out, int out_size) {
    const float* x  = (const float*)d_in[0];
    const float* Wq = (const float*)d_in[1];
    const float* Wk = (const float*)d_in[2];
    const float* Wv = (const float*)d_in[3];
    const float* Wo = (const float*)d_in[4];
    float* out = (float*)d_out;

    cudaFuncSetAttribute(attn_kernel,
                         cudaFuncAttributeMaxDynamicSharedMemorySize, 65536);
    cudaFuncSetAttribute(gemm_qkv,
                         cudaFuncAttributeMaxDynamicSharedMemorySize, GEMM_SMEM_BYTES);
    cudaFuncSetAttribute(gemm_out,
                         cudaFuncAttributeMaxDynamicSharedMemorySize, GEMM_SMEM_BYTES);

    // 0. Prep: round+transpose weights, round x
    prep_w<<<dim3(32, 32, 4), dim3(32, 8)>>>(Wq, Wk, Wv, Wo);
    prep_x<<<4096, 256>>>(x);

    // 1. RoPE (rounded qin)
    rope_kernel<<<(NTOK * 512 + 255) / 256, 256>>>(x);

    // 2. Q,K,V projections in one launch
    gemm_qkv<<<dim3(24, 16), 256, GEMM_SMEM_BYTES>>>();

    // 3. Windowed attention
    attn_kernel<<<dim3(SEQ / 128, HEADS, BATCH), 128, 65536>>>();

    // 4. Output projection -> d_out
    gemm_out<<<dim3(8, 16), 256, GEMM_SMEM_BYTES>>>(out);
    (void)in_sizes; (void)n_in; (void)out_size;
}